// round 1
// baseline (speedup 1.0000x reference)
#include <cuda_runtime.h>
#include <cstdint>

// PartialCRF forward (denominator + constrained numerator) for B=256, T=2048, K=48.
//
// Inputs (metadata order):
//   0 emissions  float32  [B,T,K]
//   1 tags       int64    [B,T]   (-1 = unlabeled)
//   2 mask       int32    [B,T]
//   3 start_transitions float32 [K]
//   4 end_transitions   float32 [K]
//   5 transitions       float32 [K,K]  (from,to)
// Output: scalar float32 = sum_b (denominator_b - numerator_b)

#define KTAGS 48
#define BATCH 256
#define NTHREADS (2 * KTAGS)   // 96: chain 0 = denominator, chain 1 = numerator

__device__ float g_chain_out[2 * BATCH];  // [0..255]=den, [256..511]=num

__global__ __launch_bounds__(NTHREADS)
void crf_forward_kernel(const float* __restrict__ emissions,
                        const long long* __restrict__ tags,
                        const int* __restrict__ mask,
                        const float* __restrict__ start_t,
                        const float* __restrict__ end_t,
                        const float* __restrict__ trans,
                        int T)
{
    const int b   = blockIdx.x;
    const int tid = threadIdx.x;
    const int c   = tid / KTAGS;        // 0 = den, 1 = num
    const int j   = tid - c * KTAGS;    // my 'to' tag
    const int wid = tid >> 5;

    // Double-buffered shared: p vectors + reduction partials
    __shared__ float sp[2][2][KTAGS];   // [buf][chain][from-tag]
    __shared__ float spart[2][4];       // [buf][partial]  0,1: chain0  2,3: chain1

    // exp(transitions[f][j]) column in registers (time-invariant)
    float et[KTAGS];
#pragma unroll
    for (int f = 0; f < KTAGS; ++f)
        et[f] = __expf(trans[f * KTAGS + j]);

    const float*     em = emissions + (size_t)b * T * KTAGS;
    const long long* tg = tags + (size_t)b * T;
    const int*       mk = mask + (size_t)b * T;

    // ---- init (t = 0) ----
    const int g0 = (int)tg[0];
    int gPrev = (c == 0) ? -1 : g0;                 // 'cur' possible-set for next step
    float alpha = start_t[j] + em[j];
    if (c == 1 && !(g0 < 0 || g0 == j)) alpha = -100.0f;   // IMPOSSIBLE

    float m = 0.0f;            // running normalizer (any value within ~±60 of max works)
    int   cnt = mk[0];         // count of valid positions (for last_idx)

    // prefetch t = 1
    float eNext  = em[KTAGS + j];
    int   gNext  = (int)tg[1];
    int   mkNext = mk[1];

    for (int t = 1; t < T; ++t) {
        const float eCur = eNext;
        const int   gCur = (c == 0) ? -1 : gNext;
        const int   mCur = mkNext;
        if (t + 1 < T) {                       // software prefetch next step
            eNext  = em[(size_t)(t + 1) * KTAGS + j];
            gNext  = (int)tg[t + 1];
            mkNext = mk[t + 1];
        }

        // p = exp(alpha - m); masked copy goes into the GEMV, unmasked into lse
        const float p  = __expf(alpha - m);
        const float pm = (gPrev < 0 || gPrev == j) ? p : 0.0f;
        const int buf = t & 1;
        sp[buf][c][j] = pm;

        // butterfly sum of unmasked p (warp1 holds two 16-lane chain segments)
        float r = p;
        r += __shfl_xor_sync(0xffffffffu, r, 1);
        r += __shfl_xor_sync(0xffffffffu, r, 2);
        r += __shfl_xor_sync(0xffffffffu, r, 4);
        r += __shfl_xor_sync(0xffffffffu, r, 8);
        if (wid != 1) r += __shfl_xor_sync(0xffffffffu, r, 16);
        if      (tid == 0)  spart[buf][0] = r;   // chain0 [0..31]
        else if (tid == 32) spart[buf][1] = r;   // chain0 [32..47]
        else if (tid == 48) spart[buf][2] = r;   // chain1 [0..15]
        else if (tid == 64) spart[buf][3] = r;   // chain1 [16..47]

        __syncthreads();

        // GEMV: s = sum_f p~[f] * exp(T[f][j])   (12x LDS.128 broadcast + 48 FFMA)
        const float4* p4 = reinterpret_cast<const float4*>(sp[buf][c]);
        float s0 = 0.f, s1 = 0.f, s2 = 0.f, s3 = 0.f;
#pragma unroll
        for (int q = 0; q < KTAGS / 4; ++q) {
            const float4 pv = p4[q];
            s0 = fmaf(pv.x, et[4 * q + 0], s0);
            s1 = fmaf(pv.y, et[4 * q + 1], s1);
            s2 = fmaf(pv.z, et[4 * q + 2], s2);
            s3 = fmaf(pv.w, et[4 * q + 3], s3);
        }
        const float s = (s0 + s1) + (s2 + s3);

        const float P   = spart[buf][2 * c] + spart[buf][2 * c + 1];
        const float lse = m + __logf(P);     // lse(alpha_{t-1}); also next normalizer

        float aNew;
        if (gCur < 0 || gCur == j) aNew = __logf(s) + m + eCur;  // possible 'to'
        else                       aNew = lse - 200.0f;          // -100(e) -100(tr)

        if (mCur) { alpha = aNew; cnt += 1; }
        gPrev = gCur;        // reference passes poss[t] as next 'cur' regardless of mask
        m = lse;
    }

    // ---- final logsumexp with end transitions ----
    const int gl = (c == 0) ? -1 : (int)tg[cnt - 1];   // tag at last_idx = sum(mask)-1
    float endv = end_t[j];
    if (c == 1 && !(gl < 0 || gl == j)) endv = 0.0f;   // repo multiplies end by poss
    const float val = alpha + endv;

    float r = __expf(val - m);
    r += __shfl_xor_sync(0xffffffffu, r, 1);
    r += __shfl_xor_sync(0xffffffffu, r, 2);
    r += __shfl_xor_sync(0xffffffffu, r, 4);
    r += __shfl_xor_sync(0xffffffffu, r, 8);
    if (wid != 1) r += __shfl_xor_sync(0xffffffffu, r, 16);
    __syncthreads();
    if      (tid == 0)  spart[0][0] = r;
    else if (tid == 32) spart[0][1] = r;
    else if (tid == 48) spart[0][2] = r;
    else if (tid == 64) spart[0][3] = r;
    __syncthreads();
    if (j == 0) {
        const float S = spart[0][2 * c] + spart[0][2 * c + 1];
        g_chain_out[c * BATCH + b] = m + __logf(S);
    }
}

__global__ void crf_reduce_kernel(float* __restrict__ out)
{
    __shared__ float sh[BATCH];
    const int i = threadIdx.x;
    sh[i] = g_chain_out[i] - g_chain_out[BATCH + i];
    __syncthreads();
#pragma unroll
    for (int stp = BATCH / 2; stp > 0; stp >>= 1) {
        if (i < stp) sh[i] += sh[i + stp];
        __syncthreads();
    }
    if (i == 0) out[0] = sh[0];
}

extern "C" void kernel_launch(void* const* d_in, const int* in_sizes, int n_in,
                              void* d_out, int out_size)
{
    const float*     emissions = (const float*)d_in[0];
    const long long* tags      = (const long long*)d_in[1];
    const int*       mask      = (const int*)d_in[2];
    const float*     start_t   = (const float*)d_in[3];
    const float*     end_t     = (const float*)d_in[4];
    const float*     trans     = (const float*)d_in[5];
    float*           out       = (float*)d_out;

    const int T = in_sizes[1] / BATCH;   // tags is [B,T]

    crf_forward_kernel<<<BATCH, NTHREADS>>>(emissions, tags, mask,
                                            start_t, end_t, trans, T);
    crf_reduce_kernel<<<1, BATCH>>>(out);
}

// round 2
// speedup vs baseline: 3.0768x; 3.0768x over previous
#include <cuda_runtime.h>
#include <cstdint>

// PartialCRF forward in the scaled-probability domain.
// B=256, T=2048 (TMAX), K=48.
//
// Inputs (metadata order):
//   0 emissions  float32 [B,T,K]
//   1 tags       int64   [B,T]   (-1 = unlabeled)
//   2 mask       int32   [B,T]
//   3 start_transitions float32 [K]
//   4 end_transitions   float32 [K]
//   5 transitions       float32 [K,K] (from,to)
// Output: scalar float32 = sum_b (denominator_b - numerator_b)

#define KTAGS 48
#define HALF  24
#define BATCH 256
#define NT    96        // 2 threads per to-tag: (j, h)  h = from-half
#define TMAX  2048

__device__ float g_chain_out[2 * BATCH];   // [0..255]=den, [256..511]=num

__global__ __launch_bounds__(NT, 4)
void crf_forward_kernel(const float* __restrict__ emissions,
                        const long long* __restrict__ tags,
                        const int* __restrict__ mask,
                        const float* __restrict__ start_t,
                        const float* __restrict__ end_t,
                        const float* __restrict__ trans,
                        int T)
{
    const int b   = blockIdx.x;
    const int c   = blockIdx.y;          // 0 = denominator, 1 = numerator
    const int tid = threadIdx.x;
    const int j   = tid >> 1;            // my 'to' tag
    const int h   = tid & 1;             // my from-half (0: f<24, 1: f>=24)

    __shared__ float sp[2][KTAGS];       // double-buffered p vector
    __shared__ float sscale;             // rescale broadcast slot
    __shared__ float sfin[KTAGS];
    __shared__ int   stag[TMAX];
    __shared__ int   smask[TMAX];

    // exp(transitions[f][j]) for my from-half (24 registers, time-invariant)
    float et[HALF];
#pragma unroll
    for (int q = 0; q < HALF; ++q)
        et[q] = __expf(trans[(h * HALF + q) * KTAGS + j]);

    const float* em   = emissions + (size_t)b * T * KTAGS;
    const int*   tg32 = (const int*)(tags + (size_t)b * T);  // low words (LE)
    const int*   mk   = mask + (size_t)b * T;

    // stage tags (numerator only) + mask into shared
    for (int i = tid; i < T; i += NT) {
        smask[i] = mk[i];
        if (c) stag[i] = tg32[2 * i];
    }
    if (tid == 0) sscale = 1.0f;
    __syncthreads();

    // ---- t = 0 ----
    float p0 = __expf(start_t[j] + em[j]);
    if (c) { int g0 = stag[0]; if (g0 >= 0 && j != g0) p0 = 0.0f; }
    if (h == 0) sp[0][j] = p0;
    float pprev  = p0;
    float logacc = 0.0f;
    int   cnt    = smask[0];

    // 4-deep emission prefetch
    float ebuf[4];
#pragma unroll
    for (int t0 = 1; t0 <= 4; ++t0) {
        int tf = (t0 < T) ? t0 : (T - 1);
        ebuf[t0 & 3] = em[(size_t)tf * KTAGS + j];
    }

#pragma unroll 4
    for (int t = 1; t < T; ++t) {
        __syncthreads();   // p_{t-1} in sp[(t-1)&1], sscale (if rewritten) visible

        // rescale bookkeeping (reads slot written at t-1 where (t-1)&3==0)
        float inv = 1.0f;
        if ((t & 3) == 1) {
            float sc = sscale;
            inv = 1.0f / sc;
            logacc += __logf(sc);
        }

        // GEMV half-sum: s_half = sum over my 24 'from' tags
        const float4* p4 =
            reinterpret_cast<const float4*>(&sp[(t - 1) & 1][h * HALF]);
        float s0 = 0.f, s1 = 0.f, s2 = 0.f, s3 = 0.f;
#pragma unroll
        for (int q = 0; q < 6; ++q) {
            const float4 pv = p4[q];
            s0 = fmaf(pv.x, et[4 * q + 0], s0);
            s1 = fmaf(pv.y, et[4 * q + 1], s1);
            s2 = fmaf(pv.z, et[4 * q + 2], s2);
            s3 = fmaf(pv.w, et[4 * q + 3], s3);
        }
        float sh = (s0 + s1) + (s2 + s3);
        sh += __shfl_xor_sync(0xffffffffu, sh, 1);   // combine the two halves

        const float e = ebuf[t & 3];
        {   // refill prefetch slot (t+4)
            int tf = t + 4; if (tf >= T) tf = T - 1;
            ebuf[t & 3] = em[(size_t)tf * KTAGS + j];
        }

        const int g  = c ? stag[t] : -1;
        const int mm = smask[t];

        float pnew = sh * __expf(e);
        if (g >= 0 && j != g) pnew = 0.0f;     // numerator: impossible 'to'
        pnew = mm ? pnew : pprev;              // mask hold
        pnew *= inv;                           // uniform rebase

        if (h == 0) sp[t & 1][j] = pnew;

        if ((t & 3) == 0) {                    // publish next rescale factor
            int sel = (g >= 0) ? g : 0;        // guaranteed-possible tag
            if (h == 0 && j == sel) sscale = fmaxf(pnew, 1e-35f);
        }

        pprev = pnew;
        cnt  += mm;
    }

    // ---- final: log( sum_j p_j * end_factor_j ) + logacc ----
    float ef = __expf(end_t[j]);
    if (c) { int gl = stag[cnt - 1]; if (gl >= 0 && j != gl) ef = 1.0f; }
    float val = pprev * ef;
    if (h == 0) sfin[j] = val;
    __syncthreads();
    if (tid == 0) {
        float s = 0.0f;
#pragma unroll
        for (int q = 0; q < KTAGS; ++q) s += sfin[q];
        g_chain_out[c * BATCH + b] = logacc + __logf(s);
    }
}

__global__ void crf_reduce_kernel(float* __restrict__ out)
{
    __shared__ float sh[BATCH];
    const int i = threadIdx.x;
    sh[i] = g_chain_out[i] - g_chain_out[BATCH + i];
    __syncthreads();
#pragma unroll
    for (int stp = BATCH / 2; stp > 0; stp >>= 1) {
        if (i < stp) sh[i] += sh[i + stp];
        __syncthreads();
    }
    if (i == 0) out[0] = sh[0];
}

extern "C" void kernel_launch(void* const* d_in, const int* in_sizes, int n_in,
                              void* d_out, int out_size)
{
    const float*     emissions = (const float*)d_in[0];
    const long long* tags      = (const long long*)d_in[1];
    const int*       mask      = (const int*)d_in[2];
    const float*     start_t   = (const float*)d_in[3];
    const float*     end_t     = (const float*)d_in[4];
    const float*     trans     = (const float*)d_in[5];
    float*           out       = (float*)d_out;

    const int T = in_sizes[1] / BATCH;   // tags is [B,T]

    dim3 grid(BATCH, 2);
    crf_forward_kernel<<<grid, NT>>>(emissions, tags, mask,
                                     start_t, end_t, trans, T);
    crf_reduce_kernel<<<1, BATCH>>>(out);
}